// round 2
// baseline (speedup 1.0000x reference)
#include <cuda_runtime.h>
#include <cuda_bf16.h>
#include <cstdint>

// Problem constants (fixed by the dataset)
#define N_NODES 50000
#define N_EDGES 600000
#define DIM 128

// Device scratch (no allocations allowed)
__device__ float g_deg[N_NODES];
__device__ float g_dinv[N_NODES];
__device__ float g_agg[(size_t)N_NODES * DIM];   // 25.6 MB
__device__ float g_Wt[DIM * DIM];                // W transposed: Wt[k][n] = W[n][k]
__device__ int   g_is64;                         // 1 if edge_index is int64, else int32

// ---------------- Kernel 0: detect edge_index dtype -----------------------
// Interpret first `cnt` entries as int64. If ALL lie in [0, n), it's int64.
// (int32 data read as int64 packs two indices; high word nonzero w.h.p.)
__global__ void k_detect(const void* __restrict__ ei, int n, int cnt) {
    __shared__ int bad;
    if (threadIdx.x == 0) bad = 0;
    __syncthreads();
    const long long* p = (const long long*)ei;
    for (int i = threadIdx.x; i < cnt; i += blockDim.x) {
        long long v = p[i];
        if (v < 0 || v >= (long long)n) bad = 1;
    }
    __syncthreads();
    if (threadIdx.x == 0) g_is64 = bad ? 0 : 1;
}

__device__ __forceinline__ int load_idx(const void* base, int i, int e, int which) {
    // which: 0 = src row, 1 = tgt row of the [2, E] array
    if (g_is64) {
        return (int)((const long long*)base)[(size_t)which * e + i];
    } else {
        return ((const int*)base)[(size_t)which * e + i];
    }
}

// ---------------- Kernel 1: deg init (self loop weight 1) ----------------
__global__ void k_init_deg(int n) {
    int i = blockIdx.x * blockDim.x + threadIdx.x;
    if (i < n) g_deg[i] = 1.0f;
}

// ---------------- Kernel 2: edge degree accumulate ----------------
__global__ void k_edge_deg(const void* __restrict__ ei,
                           const float* __restrict__ w, int e) {
    int i = blockIdx.x * blockDim.x + threadIdx.x;
    if (i < e) {
        int s = load_idx(ei, i, e, 0);
        atomicAdd(&g_deg[s], w[i]);
    }
}

// ---------------- Kernel 3: dinv = rsqrt(deg) ----------------
__global__ void k_dinv(int n) {
    int i = blockIdx.x * blockDim.x + threadIdx.x;
    if (i < n) g_dinv[i] = rsqrtf(g_deg[i]);
}

// ---------------- Kernel 4: self-loop contribution agg = x * dinv^2 -------
// one thread per float4 (32 per node)
__global__ void k_selfloop(const float* __restrict__ x, int n) {
    int i = blockIdx.x * blockDim.x + threadIdx.x;
    int node = i >> 5;
    int q = i & 31;
    if (node < n) {
        float di = g_dinv[node];
        float scale = di * di;               // dinv[src]*dinv[tgt], src==tgt
        float4 v = ((const float4*)(x + (size_t)node * DIM))[q];
        v.x *= scale; v.y *= scale; v.z *= scale; v.w *= scale;
        ((float4*)(g_agg + (size_t)node * DIM))[q] = v;
    }
}

// ---------------- Kernel 5: transpose W ----------------
__global__ void k_transpose_w(const float* __restrict__ W) {
    int i = blockIdx.x * blockDim.x + threadIdx.x;   // i = n*128 + k
    if (i < DIM * DIM) {
        int n = i >> 7;
        int k = i & 127;
        g_Wt[k * DIM + n] = W[n * DIM + k];
    }
}

// ---------------- Kernel 6: edge scatter (warp per edge) ----------------
// Each lane handles one float4 of the 128-float row; vector reduction to L2.
__global__ void k_edge_scatter(const float* __restrict__ x,
                               const void* __restrict__ ei,
                               const float* __restrict__ w, int e) {
    int gt = blockIdx.x * blockDim.x + threadIdx.x;
    int edge = gt >> 5;
    int lane = gt & 31;
    if (edge >= e) return;
    int s = load_idx(ei, edge, e, 0);
    int t = load_idx(ei, edge, e, 1);
    float wn = w[edge] * g_dinv[s] * g_dinv[t];
    float4 v = ((const float4*)(x + (size_t)s * DIM))[lane];
    v.x *= wn; v.y *= wn; v.z *= wn; v.w *= wn;
    float* dst = g_agg + (size_t)t * DIM + lane * 4;
    asm volatile("red.global.add.v4.f32 [%0], {%1, %2, %3, %4};"
                 :: "l"(dst), "f"(v.x), "f"(v.y), "f"(v.z), "f"(v.w)
                 : "memory");
}

// ---------------- Kernel 7: GEMM  out = agg @ W^T + b ----------------
// C[M,128] = A[M,128] * Bt[128,128] (Bt row-major [k][n]) + bias
// BM=128, BN=128, BK=16, 256 threads, 8x8 microtile per thread.
__global__ __launch_bounds__(256) void k_gemm(const float* __restrict__ bias,
                                              float* __restrict__ C, int M) {
    __shared__ float As[16][128];
    __shared__ float Bs[16][128];
    const float* A = g_agg;
    const float* Bt = g_Wt;

    int tid = threadIdx.x;
    int tx = tid & 15;          // 0..15 -> n block of 8
    int ty = tid >> 4;          // 0..15 -> m block of 8
    int rowBase = blockIdx.x * 128;

    float acc[8][8];
    #pragma unroll
    for (int a = 0; a < 8; a++)
        #pragma unroll
        for (int b2 = 0; b2 < 8; b2++) acc[a][b2] = 0.0f;

    for (int kt = 0; kt < DIM; kt += 16) {
        // Load A tile: 128 rows x 16 k = 512 float4
        #pragma unroll
        for (int j = 0; j < 2; j++) {
            int i4 = tid + j * 256;          // 0..511
            int m = i4 >> 2;                 // row within tile
            int kq = i4 & 3;                 // which float4 of the 16 k
            int gm = rowBase + m;
            float4 v = make_float4(0.f, 0.f, 0.f, 0.f);
            if (gm < M) v = ((const float4*)(A + (size_t)gm * DIM + kt))[kq];
            As[kq * 4 + 0][m] = v.x;
            As[kq * 4 + 1][m] = v.y;
            As[kq * 4 + 2][m] = v.z;
            As[kq * 4 + 3][m] = v.w;
        }
        // Load B tile: 16 k x 128 n = 512 float4 (coalesced from Wt)
        #pragma unroll
        for (int j = 0; j < 2; j++) {
            int i4 = tid + j * 256;
            int k = i4 >> 5;
            int nq = i4 & 31;
            float4 v = ((const float4*)(Bt + (size_t)(kt + k) * DIM))[nq];
            ((float4*)&Bs[k][0])[nq] = v;
        }
        __syncthreads();

        #pragma unroll
        for (int k = 0; k < 16; k++) {
            float ra[8], rb[8];
            #pragma unroll
            for (int a = 0; a < 8; a++) ra[a] = As[k][ty * 8 + a];
            #pragma unroll
            for (int b2 = 0; b2 < 8; b2++) rb[b2] = Bs[k][tx * 8 + b2];
            #pragma unroll
            for (int a = 0; a < 8; a++)
                #pragma unroll
                for (int b2 = 0; b2 < 8; b2++)
                    acc[a][b2] += ra[a] * rb[b2];
        }
        __syncthreads();
    }

    // Epilogue: add bias, store
    #pragma unroll
    for (int a = 0; a < 8; a++) {
        int gm = rowBase + ty * 8 + a;
        if (gm < M) {
            #pragma unroll
            for (int b2 = 0; b2 < 8; b2 += 4) {
                int n = tx * 8 + b2;
                float4 o;
                o.x = acc[a][b2 + 0] + bias[n + 0];
                o.y = acc[a][b2 + 1] + bias[n + 1];
                o.z = acc[a][b2 + 2] + bias[n + 2];
                o.w = acc[a][b2 + 3] + bias[n + 3];
                *((float4*)(C + (size_t)gm * DIM + n)) = o;
            }
        }
    }
}

extern "C" void kernel_launch(void* const* d_in, const int* in_sizes, int n_in,
                              void* d_out, int out_size) {
    const float* x  = (const float*)d_in[0];
    const void*  ei = d_in[1];                 // [2, E] int32 OR int64
    const float* ew = (const float*)d_in[2];
    const float* W  = (const float*)d_in[3];
    const float* b  = (const float*)d_in[4];
    float* out = (float*)d_out;

    int N = in_sizes[0] / DIM;
    int E = in_sizes[1] / 2;

    int detect_cnt = (E < 1024) ? E : 1024;
    k_detect<<<1, 256>>>(ei, N, detect_cnt);
    k_init_deg<<<(N + 255) / 256, 256>>>(N);
    k_edge_deg<<<(E + 255) / 256, 256>>>(ei, ew, E);
    k_dinv<<<(N + 255) / 256, 256>>>(N);
    k_selfloop<<<((N * 32) + 255) / 256, 256>>>(x, N);
    k_transpose_w<<<(DIM * DIM + 255) / 256, 256>>>(W);
    {
        long long total = (long long)E * 32;
        int blocks = (int)((total + 255) / 256);
        k_edge_scatter<<<blocks, 256>>>(x, ei, ew, E);
    }
    k_gemm<<<(N + 127) / 128, 256>>>(b, out, N);
}

// round 3
// speedup vs baseline: 1.0959x; 1.0959x over previous
#include <cuda_runtime.h>
#include <cuda_bf16.h>
#include <cstdint>

#define N_NODES 50000
#define N_EDGES 600000
#define DIM 128

// Device scratch (zero-initialized at module load; no allocations allowed)
__device__ float g_deg[N_NODES];                 // accumulates, reset to 0 each call
__device__ float g_dinv[N_NODES];
__device__ float g_y[(size_t)N_NODES * DIM];     // y = x @ W^T
__device__ int   g_is64;

// ---------------- packed fp32x2 helpers ----------------
__device__ __forceinline__ unsigned long long pk2(float lo, float hi) {
    unsigned long long r;
    asm("mov.b64 %0, {%1, %2};" : "=l"(r) : "f"(lo), "f"(hi));
    return r;
}
__device__ __forceinline__ void fma2(unsigned long long& d,
                                     unsigned long long a, unsigned long long b) {
    asm("fma.rn.f32x2 %0, %1, %2, %0;" : "+l"(d) : "l"(a), "l"(b));
}
__device__ __forceinline__ float2 up2(unsigned long long v) {
    float2 f;
    asm("mov.b64 {%0, %1}, %2;" : "=f"(f.x), "=f"(f.y) : "l"(v));
    return f;
}

// ---------------- Kernel 0: detect edge_index dtype ----------------
// If all first `cnt` int64-interpreted entries are in [0, n), data is int64;
// int32 data read as int64 packs two indices (high word nonzero w.h.p.).
__global__ void k_detect(const void* __restrict__ ei, int n, int cnt) {
    __shared__ int bad;
    if (threadIdx.x == 0) bad = 0;
    __syncthreads();
    const long long* p = (const long long*)ei;
    for (int i = threadIdx.x; i < cnt; i += blockDim.x) {
        long long v = p[i];
        if (v < 0 || v >= (long long)n) bad = 1;
    }
    __syncthreads();
    if (threadIdx.x == 0) g_is64 = bad ? 0 : 1;
}

__device__ __forceinline__ int load_idx(const void* base, int i, int e, int which) {
    if (g_is64) return (int)((const long long*)base)[(size_t)which * e + i];
    return ((const int*)base)[(size_t)which * e + i];
}

// ---------------- Kernel 1: edge degree accumulate (g_deg starts at 0) ----
__global__ void k_edge_deg(const void* __restrict__ ei,
                           const float* __restrict__ w, int e) {
    int i = blockIdx.x * blockDim.x + threadIdx.x;
    if (i < e) {
        int s = load_idx(ei, i, e, 0);
        atomicAdd(&g_deg[s], w[i]);
    }
}

// ---------------- Kernel 2: dinv = rsqrt(deg + 1), reset deg --------------
__global__ void k_dinv(int n) {
    int i = blockIdx.x * blockDim.x + threadIdx.x;
    if (i < n) {
        g_dinv[i] = rsqrtf(g_deg[i] + 1.0f);   // +1 = self-loop weight
        g_deg[i] = 0.0f;                        // restore zeroed state for next call
    }
}

// ---------------- Kernel 3: y = x @ W^T ; out = y*dinv^2 + bias -----------
// BM=128, BN=128, BK=32, 256 threads, 8x8 microtile, packed f32x2 FMA.
__global__ __launch_bounds__(256) void k_gemm(const float* __restrict__ x,
                                              const float* __restrict__ W,
                                              const float* __restrict__ bias,
                                              float* __restrict__ out, int M) {
    __shared__ float As[32][128];   // As[k][m]
    __shared__ float Bs[32][128];   // Bs[k][n] = W[n][k]

    int tid = threadIdx.x;
    int tx = tid & 15;              // n block of 8
    int ty = tid >> 4;              // m block of 8
    int rowBase = blockIdx.x * 128;

    unsigned long long acc[8][4];
    #pragma unroll
    for (int a = 0; a < 8; a++)
        #pragma unroll
        for (int b2 = 0; b2 < 4; b2++) acc[a][b2] = 0ULL;

    for (int kt = 0; kt < DIM; kt += 32) {
        // A tile: 128 rows x 32 k = 1024 float4, 4 per thread
        #pragma unroll
        for (int j = 0; j < 4; j++) {
            int i4 = tid + j * 256;
            int m  = i4 >> 3;           // row in tile
            int kq = i4 & 7;            // which float4 of 32 k
            int gm = rowBase + m;
            float4 v = make_float4(0.f, 0.f, 0.f, 0.f);
            if (gm < M) v = *(const float4*)(x + (size_t)gm * DIM + kt + kq * 4);
            As[kq * 4 + 0][m] = v.x;
            As[kq * 4 + 1][m] = v.y;
            As[kq * 4 + 2][m] = v.z;
            As[kq * 4 + 3][m] = v.w;
        }
        // B tile (transpose fused): Bs[k][n] = W[n][k]
        #pragma unroll
        for (int j = 0; j < 4; j++) {
            int i4 = tid + j * 256;
            int n  = i4 >> 3;
            int kq = i4 & 7;
            float4 v = *(const float4*)(W + (size_t)n * DIM + kt + kq * 4);
            Bs[kq * 4 + 0][n] = v.x;
            Bs[kq * 4 + 1][n] = v.y;
            Bs[kq * 4 + 2][n] = v.z;
            Bs[kq * 4 + 3][n] = v.w;
        }
        __syncthreads();

        #pragma unroll
        for (int k = 0; k < 32; k++) {
            float4 a0 = *(const float4*)&As[k][ty * 8];
            float4 a1 = *(const float4*)&As[k][ty * 8 + 4];
            float4 b0 = *(const float4*)&Bs[k][tx * 8];
            float4 b1 = *(const float4*)&Bs[k][tx * 8 + 4];
            unsigned long long bp[4] = {pk2(b0.x, b0.y), pk2(b0.z, b0.w),
                                        pk2(b1.x, b1.y), pk2(b1.z, b1.w)};
            float aa[8] = {a0.x, a0.y, a0.z, a0.w, a1.x, a1.y, a1.z, a1.w};
            #pragma unroll
            for (int a = 0; a < 8; a++) {
                unsigned long long ad = pk2(aa[a], aa[a]);
                #pragma unroll
                for (int b2 = 0; b2 < 4; b2++) fma2(acc[a][b2], ad, bp[b2]);
            }
        }
        __syncthreads();
    }

    // Epilogue: write y, and out = y*dinv^2 + bias (self-loop + bias fused)
    float4 bi0 = *(const float4*)(bias + tx * 8);
    float4 bi1 = *(const float4*)(bias + tx * 8 + 4);
    #pragma unroll
    for (int a = 0; a < 8; a++) {
        int gm = rowBase + ty * 8 + a;
        if (gm < M) {
            float di = g_dinv[gm];
            float sc = di * di;
            float2 r0 = up2(acc[a][0]), r1 = up2(acc[a][1]);
            float2 r2 = up2(acc[a][2]), r3 = up2(acc[a][3]);
            float* yrow = g_y + (size_t)gm * DIM + tx * 8;
            *(float4*)(yrow)     = make_float4(r0.x, r0.y, r1.x, r1.y);
            *(float4*)(yrow + 4) = make_float4(r2.x, r2.y, r3.x, r3.y);
            float* orow = out + (size_t)gm * DIM + tx * 8;
            *(float4*)(orow)     = make_float4(r0.x * sc + bi0.x, r0.y * sc + bi0.y,
                                               r1.x * sc + bi0.z, r1.y * sc + bi0.w);
            *(float4*)(orow + 4) = make_float4(r2.x * sc + bi1.x, r2.y * sc + bi1.y,
                                               r3.x * sc + bi1.z, r3.y * sc + bi1.w);
        }
    }
}

// ---------------- Kernel 4/5: edge scatter (warp per 4 edges) -------------
// Each warp: batch-load meta for 4 edges, 4 independent row gathers in
// flight, then 4 vector reductions into out.
__global__ void k_edge_scatter(const void* __restrict__ ei,
                               const float* __restrict__ w,
                               float* __restrict__ out,
                               int e, int eoff, int ecount) {
    int warp = (blockIdx.x * blockDim.x + threadIdx.x) >> 5;
    int lane = threadIdx.x & 31;
    int base = eoff + warp * 4;
    if (warp * 4 >= ecount) return;
    int cnt = ecount - warp * 4;
    if (cnt > 4) cnt = 4;

    int s[4], t[4];
    float ww[4];
    if (g_is64) {
        const long long* p = (const long long*)ei;
        #pragma unroll
        for (int j = 0; j < 4; j++) {
            int idx = (j < cnt) ? base + j : base;
            s[j] = (int)p[idx];
            t[j] = (int)p[(size_t)e + idx];
            ww[j] = w[idx];
        }
    } else {
        const int* p = (const int*)ei;
        if (cnt == 4 && ((base & 3) == 0) && ((e & 3) == 0)) {
            int4 sv = *(const int4*)(p + base);
            int4 tv = *(const int4*)(p + e + base);
            float4 wv = *(const float4*)(w + base);
            s[0] = sv.x; s[1] = sv.y; s[2] = sv.z; s[3] = sv.w;
            t[0] = tv.x; t[1] = tv.y; t[2] = tv.z; t[3] = tv.w;
            ww[0] = wv.x; ww[1] = wv.y; ww[2] = wv.z; ww[3] = wv.w;
        } else {
            #pragma unroll
            for (int j = 0; j < 4; j++) {
                int idx = (j < cnt) ? base + j : base;
                s[j] = p[idx];
                t[j] = p[e + idx];
                ww[j] = w[idx];
            }
        }
    }

    float wn[4];
    #pragma unroll
    for (int j = 0; j < 4; j++) wn[j] = ww[j] * g_dinv[s[j]] * g_dinv[t[j]];

    float4 v[4];
    #pragma unroll
    for (int j = 0; j < 4; j++)
        v[j] = ((const float4*)(g_y + (size_t)s[j] * DIM))[lane];

    #pragma unroll
    for (int j = 0; j < 4; j++) {
        if (j < cnt) {
            float a0 = v[j].x * wn[j], a1 = v[j].y * wn[j];
            float a2 = v[j].z * wn[j], a3 = v[j].w * wn[j];
            float* dst = out + (size_t)t[j] * DIM + lane * 4;
            asm volatile("red.global.add.v4.f32 [%0], {%1, %2, %3, %4};"
                         :: "l"(dst), "f"(a0), "f"(a1), "f"(a2), "f"(a3)
                         : "memory");
        }
    }
}

extern "C" void kernel_launch(void* const* d_in, const int* in_sizes, int n_in,
                              void* d_out, int out_size) {
    const float* x  = (const float*)d_in[0];
    const void*  ei = d_in[1];                 // [2, E] int32 OR int64
    const float* ew = (const float*)d_in[2];
    const float* W  = (const float*)d_in[3];
    const float* b  = (const float*)d_in[4];
    float* out = (float*)d_out;

    int N = in_sizes[0] / DIM;
    int E = in_sizes[1] / 2;

    int detect_cnt = (E < 1024) ? E : 1024;
    k_detect<<<1, 256>>>(ei, N, detect_cnt);                       // launch 0
    k_edge_deg<<<(E + 255) / 256, 256>>>(ei, ew, E);               // launch 1
    k_dinv<<<(N + 255) / 256, 256>>>(N);                           // launch 2
    k_gemm<<<(N + 127) / 128, 256>>>(x, W, b, out, N);             // launch 3

    int Eh = E / 2;
    Eh &= ~3;                       // keep half-boundary 4-aligned for int4 path
    int Er = E - Eh;
    {
        long long th0 = ((long long)(Eh + 3) / 4) * 32;
        int blocks0 = (int)((th0 + 255) / 256);
        if (blocks0 > 0)
            k_edge_scatter<<<blocks0, 256>>>(ei, ew, out, E, 0, Eh);   // launch 4
        long long th1 = ((long long)(Er + 3) / 4) * 32;
        int blocks1 = (int)((th1 + 255) / 256);
        if (blocks1 > 0)
            k_edge_scatter<<<blocks1, 256>>>(ei, ew, out, E, Eh, Er);  // launch 5
    }
}

// round 4
// speedup vs baseline: 1.1699x; 1.0675x over previous
#include <cuda_runtime.h>
#include <cuda_bf16.h>
#include <cstdint>

#define N_NODES 50000
#define N_EDGES 600000
#define DIM 128

// Device scratch (zero-initialized at module load; no allocations allowed)
__device__ float g_deg[N_NODES];                 // accumulates, reset to 0 each call
__device__ float g_dinv[N_NODES];
__device__ float g_y[(size_t)N_NODES * DIM];     // y = x @ W^T
__device__ int   g_is64;

// ---------------- packed fp32x2 helpers ----------------
__device__ __forceinline__ unsigned long long pk2(float lo, float hi) {
    unsigned long long r;
    asm("mov.b64 %0, {%1, %2};" : "=l"(r) : "f"(lo), "f"(hi));
    return r;
}
__device__ __forceinline__ void fma2(unsigned long long& d,
                                     unsigned long long a, unsigned long long b) {
    asm("fma.rn.f32x2 %0, %1, %2, %0;" : "+l"(d) : "l"(a), "l"(b));
}
__device__ __forceinline__ float2 up2(unsigned long long v) {
    float2 f;
    asm("mov.b64 {%0, %1}, %2;" : "=f"(f.x), "=f"(f.y) : "l"(v));
    return f;
}

// ---------------- Kernel 0: detect edge_index dtype ----------------
__global__ void k_detect(const void* __restrict__ ei, int n, int cnt) {
    __shared__ int bad;
    if (threadIdx.x == 0) bad = 0;
    __syncthreads();
    const long long* p = (const long long*)ei;
    for (int i = threadIdx.x; i < cnt; i += blockDim.x) {
        long long v = p[i];
        if (v < 0 || v >= (long long)n) bad = 1;
    }
    __syncthreads();
    if (threadIdx.x == 0) g_is64 = bad ? 0 : 1;
}

__device__ __forceinline__ int load_idx(const void* base, int i, int e, int which) {
    if (g_is64) return (int)((const long long*)base)[(size_t)which * e + i];
    return ((const int*)base)[(size_t)which * e + i];
}

// ---------------- Kernel 1: edge degree accumulate (g_deg starts at 0) ----
__global__ void k_edge_deg(const void* __restrict__ ei,
                           const float* __restrict__ w, int e) {
    int i = blockIdx.x * blockDim.x + threadIdx.x;
    if (i < e) {
        int s = load_idx(ei, i, e, 0);
        atomicAdd(&g_deg[s], w[i]);
    }
}

// ---------------- Kernel 2: dinv = rsqrt(deg + 1), reset deg --------------
__global__ void k_dinv(int n) {
    int i = blockIdx.x * blockDim.x + threadIdx.x;
    if (i < n) {
        g_dinv[i] = rsqrtf(g_deg[i] + 1.0f);   // +1 = self-loop weight
        g_deg[i] = 0.0f;                        // restore zeroed state
    }
}

// ---------------- Kernel 3: y = x @ W^T ; out = y*dinv^2 + bias -----------
// BM=128, BN=128, BK=32, 256 threads, 8x8 microtile, f32x2 FMA.
// Pitch-132 smem (bank-spread transpose stores, 16B-aligned reads),
// 2 CTAs/SM, register prefetch of next k-tile.
#define PITCH 132
__global__ __launch_bounds__(256, 2) void k_gemm(const float* __restrict__ x,
                                                 const float* __restrict__ W,
                                                 const float* __restrict__ bias,
                                                 float* __restrict__ out, int M) {
    __shared__ float As[32 * PITCH];   // As[k][m], pitch 132
    __shared__ float Bs[32 * PITCH];   // Bs[k][n] = W[n][k]

    int tid = threadIdx.x;
    int tx = tid & 15;              // n block of 8
    int ty = tid >> 4;              // m block of 8
    int rowBase = blockIdx.x * 128;

    // load-phase mapping: i4 = tid + j*256; m/n = i4>>3, kq = i4&7
    int lm = tid >> 3;              // row/col index for j=0 (j adds 32)
    int kq = tid & 7;

    unsigned long long acc[8][4];
    #pragma unroll
    for (int a = 0; a < 8; a++)
        #pragma unroll
        for (int b2 = 0; b2 < 4; b2++) acc[a][b2] = 0ULL;

    float4 pA[4], pB[4];
    // prefetch k-tile 0
    #pragma unroll
    for (int j = 0; j < 4; j++) {
        int m = lm + j * 32;
        int gm = rowBase + m;
        pA[j] = (gm < M) ? *(const float4*)(x + (size_t)gm * DIM + kq * 4)
                         : make_float4(0.f, 0.f, 0.f, 0.f);
        pB[j] = *(const float4*)(W + (size_t)m * DIM + kq * 4);
    }

    #pragma unroll
    for (int kt = 0; kt < DIM; kt += 32) {
        // store prefetched tile to smem (transpose k-minor -> k-major)
        #pragma unroll
        for (int j = 0; j < 4; j++) {
            int m = lm + j * 32;
            As[(kq * 4 + 0) * PITCH + m] = pA[j].x;
            As[(kq * 4 + 1) * PITCH + m] = pA[j].y;
            As[(kq * 4 + 2) * PITCH + m] = pA[j].z;
            As[(kq * 4 + 3) * PITCH + m] = pA[j].w;
            Bs[(kq * 4 + 0) * PITCH + m] = pB[j].x;
            Bs[(kq * 4 + 1) * PITCH + m] = pB[j].y;
            Bs[(kq * 4 + 2) * PITCH + m] = pB[j].z;
            Bs[(kq * 4 + 3) * PITCH + m] = pB[j].w;
        }
        __syncthreads();

        // prefetch next k-tile while computing this one
        if (kt + 32 < DIM) {
            #pragma unroll
            for (int j = 0; j < 4; j++) {
                int m = lm + j * 32;
                int gm = rowBase + m;
                pA[j] = (gm < M) ? *(const float4*)(x + (size_t)gm * DIM + kt + 32 + kq * 4)
                                 : make_float4(0.f, 0.f, 0.f, 0.f);
                pB[j] = *(const float4*)(W + (size_t)m * DIM + kt + 32 + kq * 4);
            }
        }

        #pragma unroll
        for (int k = 0; k < 32; k++) {
            float4 a0 = *(const float4*)&As[k * PITCH + ty * 8];
            float4 a1 = *(const float4*)&As[k * PITCH + ty * 8 + 4];
            float4 b0 = *(const float4*)&Bs[k * PITCH + tx * 8];
            float4 b1 = *(const float4*)&Bs[k * PITCH + tx * 8 + 4];
            unsigned long long bp[4] = {pk2(b0.x, b0.y), pk2(b0.z, b0.w),
                                        pk2(b1.x, b1.y), pk2(b1.z, b1.w)};
            float aa[8] = {a0.x, a0.y, a0.z, a0.w, a1.x, a1.y, a1.z, a1.w};
            #pragma unroll
            for (int a = 0; a < 8; a++) {
                unsigned long long ad = pk2(aa[a], aa[a]);
                #pragma unroll
                for (int b2 = 0; b2 < 4; b2++) fma2(acc[a][b2], ad, bp[b2]);
            }
        }
        __syncthreads();
    }

    // Epilogue: write y, and out = y*dinv^2 + bias (self-loop + bias fused)
    float4 bi0 = *(const float4*)(bias + tx * 8);
    float4 bi1 = *(const float4*)(bias + tx * 8 + 4);
    #pragma unroll
    for (int a = 0; a < 8; a++) {
        int gm = rowBase + ty * 8 + a;
        if (gm < M) {
            float di = g_dinv[gm];
            float sc = di * di;
            float2 r0 = up2(acc[a][0]), r1 = up2(acc[a][1]);
            float2 r2 = up2(acc[a][2]), r3 = up2(acc[a][3]);
            float* yrow = g_y + (size_t)gm * DIM + tx * 8;
            *(float4*)(yrow)     = make_float4(r0.x, r0.y, r1.x, r1.y);
            *(float4*)(yrow + 4) = make_float4(r2.x, r2.y, r3.x, r3.y);
            float* orow = out + (size_t)gm * DIM + tx * 8;
            *(float4*)(orow)     = make_float4(r0.x * sc + bi0.x, r0.y * sc + bi0.y,
                                               r1.x * sc + bi0.z, r1.y * sc + bi0.w);
            *(float4*)(orow + 4) = make_float4(r2.x * sc + bi1.x, r2.y * sc + bi1.y,
                                               r3.x * sc + bi1.z, r3.y * sc + bi1.w);
        }
    }
}

// ---------------- Kernel 4/5: edge scatter (warp per 4 edges) -------------
__global__ void k_edge_scatter(const void* __restrict__ ei,
                               const float* __restrict__ w,
                               float* __restrict__ out,
                               int e, int eoff, int ecount) {
    int warp = (blockIdx.x * blockDim.x + threadIdx.x) >> 5;
    int lane = threadIdx.x & 31;
    int base = eoff + warp * 4;
    if (warp * 4 >= ecount) return;
    int cnt = ecount - warp * 4;
    if (cnt > 4) cnt = 4;

    int s[4], t[4];
    float ww[4];
    if (g_is64) {
        const long long* p = (const long long*)ei;
        #pragma unroll
        for (int j = 0; j < 4; j++) {
            int idx = (j < cnt) ? base + j : base;
            s[j] = (int)p[idx];
            t[j] = (int)p[(size_t)e + idx];
            ww[j] = w[idx];
        }
    } else {
        const int* p = (const int*)ei;
        if (cnt == 4 && ((base & 3) == 0) && ((e & 3) == 0)) {
            int4 sv = *(const int4*)(p + base);
            int4 tv = *(const int4*)(p + e + base);
            float4 wv = *(const float4*)(w + base);
            s[0] = sv.x; s[1] = sv.y; s[2] = sv.z; s[3] = sv.w;
            t[0] = tv.x; t[1] = tv.y; t[2] = tv.z; t[3] = tv.w;
            ww[0] = wv.x; ww[1] = wv.y; ww[2] = wv.z; ww[3] = wv.w;
        } else {
            #pragma unroll
            for (int j = 0; j < 4; j++) {
                int idx = (j < cnt) ? base + j : base;
                s[j] = p[idx];
                t[j] = p[e + idx];
                ww[j] = w[idx];
            }
        }
    }

    float wn[4];
    #pragma unroll
    for (int j = 0; j < 4; j++) wn[j] = ww[j] * g_dinv[s[j]] * g_dinv[t[j]];

    float4 v[4];
    #pragma unroll
    for (int j = 0; j < 4; j++)
        v[j] = ((const float4*)(g_y + (size_t)s[j] * DIM))[lane];

    #pragma unroll
    for (int j = 0; j < 4; j++) {
        if (j < cnt) {
            float a0 = v[j].x * wn[j], a1 = v[j].y * wn[j];
            float a2 = v[j].z * wn[j], a3 = v[j].w * wn[j];
            float* dst = out + (size_t)t[j] * DIM + lane * 4;
            asm volatile("red.global.add.v4.f32 [%0], {%1, %2, %3, %4};"
                         :: "l"(dst), "f"(a0), "f"(a1), "f"(a2), "f"(a3)
                         : "memory");
        }
    }
}

extern "C" void kernel_launch(void* const* d_in, const int* in_sizes, int n_in,
                              void* d_out, int out_size) {
    const float* x  = (const float*)d_in[0];
    const void*  ei = d_in[1];                 // [2, E] int32 OR int64
    const float* ew = (const float*)d_in[2];
    const float* W  = (const float*)d_in[3];
    const float* b  = (const float*)d_in[4];
    float* out = (float*)d_out;

    int N = in_sizes[0] / DIM;
    int E = in_sizes[1] / 2;

    int detect_cnt = (E < 1024) ? E : 1024;
    k_detect<<<1, 256>>>(ei, N, detect_cnt);                       // launch 0
    k_edge_deg<<<(E + 255) / 256, 256>>>(ei, ew, E);               // launch 1
    k_dinv<<<(N + 255) / 256, 256>>>(N);                           // launch 2
    k_gemm<<<(N + 127) / 128, 256>>>(x, W, b, out, N);             // launch 3

    int Eh = E / 2;
    Eh &= ~3;                       // keep half-boundary 4-aligned for int4 path
    int Er = E - Eh;
    {
        long long th0 = ((long long)(Eh + 3) / 4) * 32;
        int blocks0 = (int)((th0 + 255) / 256);
        if (blocks0 > 0)
            k_edge_scatter<<<blocks0, 256>>>(ei, ew, out, E, 0, Eh);   // launch 4
        long long th1 = ((long long)(Er + 3) / 4) * 32;
        int blocks1 = (int)((th1 + 255) / 256);
        if (blocks1 > 0)
            k_edge_scatter<<<blocks1, 256>>>(ei, ew, out, E, Eh, Er);  // launch 5
    }
}

// round 5
// speedup vs baseline: 1.3571x; 1.1600x over previous
#include <cuda_runtime.h>
#include <cuda_bf16.h>
#include <cstdint>

#define N_NODES 50000
#define N_EDGES 600000
#define DIM 128

// Device scratch (zero-initialized at load; restored to invariants each call)
__device__ float g_deg[N_NODES];                  // zeroed again in k_scan3
__device__ float g_dinv[N_NODES];
__device__ float g_y[(size_t)N_NODES * DIM];      // y = x @ W^T
__device__ int   g_cnt[N_NODES];                  // in-degree counts; zeroed in k_aggregate
__device__ int   g_rowptr[N_NODES + 1];
__device__ int   g_cursor[N_NODES];
__device__ int   g_bsum[256];
__device__ int   g_esrc[N_EDGES];
__device__ float g_ewn[N_EDGES];
__device__ int   g_is64;

// ---------------- packed fp32x2 helpers ----------------
__device__ __forceinline__ unsigned long long pk2(float lo, float hi) {
    unsigned long long r;
    asm("mov.b64 %0, {%1, %2};" : "=l"(r) : "f"(lo), "f"(hi));
    return r;
}
__device__ __forceinline__ void fma2(unsigned long long& d,
                                     unsigned long long a, unsigned long long b) {
    asm("fma.rn.f32x2 %0, %1, %2, %0;" : "+l"(d) : "l"(a), "l"(b));
}
__device__ __forceinline__ float2 up2(unsigned long long v) {
    float2 f;
    asm("mov.b64 {%0, %1}, %2;" : "=f"(f.x), "=f"(f.y) : "l"(v));
    return f;
}

// ---------------- dtype detect (int32 vs int64 edge_index) ----------------
__global__ void k_detect(const void* __restrict__ ei, int n, int cnt) {
    __shared__ int bad;
    if (threadIdx.x == 0) bad = 0;
    __syncthreads();
    const long long* p = (const long long*)ei;
    for (int i = threadIdx.x; i < cnt; i += blockDim.x) {
        long long v = p[i];
        if (v < 0 || v >= (long long)n) bad = 1;
    }
    __syncthreads();
    if (threadIdx.x == 0) g_is64 = bad ? 0 : 1;
}

__device__ __forceinline__ int load_idx(const void* base, int i, int e, int which) {
    if (g_is64) return (int)((const long long*)base)[(size_t)which * e + i];
    return ((const int*)base)[(size_t)which * e + i];
}

// ---------------- edge pass 1: weighted out-degree + in-count ------------
__global__ void k_edge_deg(const void* __restrict__ ei,
                           const float* __restrict__ w, int e) {
    int i = blockIdx.x * blockDim.x + threadIdx.x;
    if (i < e) {
        int s = load_idx(ei, i, e, 0);
        int t = load_idx(ei, i, e, 1);
        atomicAdd(&g_deg[s], w[i]);
        atomicAdd(&g_cnt[t], 1);
    }
}

// ---------------- scan stage 1: per-block sums of counts ------------------
__global__ void k_scan1(int n) {
    __shared__ int sh[256];
    int i = blockIdx.x * 256 + threadIdx.x;
    int v = (i < n) ? g_cnt[i] : 0;
    sh[threadIdx.x] = v;
    __syncthreads();
    for (int off = 128; off > 0; off >>= 1) {
        if (threadIdx.x < off) sh[threadIdx.x] += sh[threadIdx.x + off];
        __syncthreads();
    }
    if (threadIdx.x == 0) g_bsum[blockIdx.x] = sh[0];
}

// ---------------- scan stage 2: rowptr/cursor + dinv + deg reset ----------
// Every block redundantly scans the (<=256) block sums, then scans its own
// 256 counts. Also computes dinv = rsqrt(deg+1) and resets deg.
__global__ void k_scan3(int n, int nb, int e) {
    __shared__ int shb[256];
    __shared__ int sh[256];
    int tid = threadIdx.x;
    int bid = blockIdx.x;

    int bv = (tid < nb) ? g_bsum[tid] : 0;
    shb[tid] = bv;
    __syncthreads();
    #pragma unroll
    for (int off = 1; off < 256; off <<= 1) {
        int t2 = (tid >= off) ? shb[tid - off] : 0;
        __syncthreads();
        shb[tid] += t2;
        __syncthreads();
    }
    int base = (bid > 0) ? shb[bid - 1] : 0;

    int i = bid * 256 + tid;
    int v = (i < n) ? g_cnt[i] : 0;
    sh[tid] = v;
    __syncthreads();
    #pragma unroll
    for (int off = 1; off < 256; off <<= 1) {
        int t2 = (tid >= off) ? sh[tid - off] : 0;
        __syncthreads();
        sh[tid] += t2;
        __syncthreads();
    }
    if (i < n) {
        int rp = base + sh[tid] - v;     // exclusive
        g_rowptr[i] = rp;
        g_cursor[i] = rp;
        float d = g_deg[i];
        g_dinv[i] = rsqrtf(d + 1.0f);    // +1 = self-loop weight
        g_deg[i] = 0.0f;                 // restore zero for next call
    }
    if (i == 0) g_rowptr[n] = e;
}

// ---------------- fill CSR buckets: (src, normalized weight) --------------
__global__ void k_fill(const void* __restrict__ ei,
                       const float* __restrict__ w, int e) {
    int i = blockIdx.x * blockDim.x + threadIdx.x;
    if (i < e) {
        int s = load_idx(ei, i, e, 0);
        int t = load_idx(ei, i, e, 1);
        float wn = w[i] * g_dinv[s] * g_dinv[t];
        int pos = atomicAdd(&g_cursor[t], 1);
        g_esrc[pos] = s;
        g_ewn[pos] = wn;
    }
}

// ---------------- GEMM: y = x @ W^T (conflict-free B reads) ---------------
// BM=128, BN=128, BK=32, 256 threads, 8x8 microtile, f32x2 FMA, 2 CTAs/SM.
// B fragment split: float4 at row index tx and tx+16 -> an 8-lane LDS.128
// phase hits 8 consecutive float4s = all 32 banks, conflict-free.
#define PITCH 132
__global__ __launch_bounds__(256, 2) void k_gemm(const float* __restrict__ x,
                                                 const float* __restrict__ W,
                                                 int M) {
    __shared__ float As[32 * PITCH];   // As[k][m]
    __shared__ float Bs[32 * PITCH];   // Bs[k][n] = W[n][k]

    int tid = threadIdx.x;
    int tx = tid & 15;
    int ty = tid >> 4;
    int rowBase = blockIdx.x * 128;

    int lm = tid >> 3;
    int kq = tid & 7;

    unsigned long long acc[8][4];
    #pragma unroll
    for (int a = 0; a < 8; a++)
        #pragma unroll
        for (int b2 = 0; b2 < 4; b2++) acc[a][b2] = 0ULL;

    float4 pA[4], pB[4];
    #pragma unroll
    for (int j = 0; j < 4; j++) {
        int m = lm + j * 32;
        int gm = rowBase + m;
        pA[j] = (gm < M) ? *(const float4*)(x + (size_t)gm * DIM + kq * 4)
                         : make_float4(0.f, 0.f, 0.f, 0.f);
        pB[j] = *(const float4*)(W + (size_t)m * DIM + kq * 4);
    }

    #pragma unroll
    for (int kt = 0; kt < DIM; kt += 32) {
        #pragma unroll
        for (int j = 0; j < 4; j++) {
            int m = lm + j * 32;
            As[(kq * 4 + 0) * PITCH + m] = pA[j].x;
            As[(kq * 4 + 1) * PITCH + m] = pA[j].y;
            As[(kq * 4 + 2) * PITCH + m] = pA[j].z;
            As[(kq * 4 + 3) * PITCH + m] = pA[j].w;
            Bs[(kq * 4 + 0) * PITCH + m] = pB[j].x;
            Bs[(kq * 4 + 1) * PITCH + m] = pB[j].y;
            Bs[(kq * 4 + 2) * PITCH + m] = pB[j].z;
            Bs[(kq * 4 + 3) * PITCH + m] = pB[j].w;
        }
        __syncthreads();

        if (kt + 32 < DIM) {
            #pragma unroll
            for (int j = 0; j < 4; j++) {
                int m = lm + j * 32;
                int gm = rowBase + m;
                pA[j] = (gm < M) ? *(const float4*)(x + (size_t)gm * DIM + kt + 32 + kq * 4)
                                 : make_float4(0.f, 0.f, 0.f, 0.f);
                pB[j] = *(const float4*)(W + (size_t)m * DIM + kt + 32 + kq * 4);
            }
        }

        #pragma unroll
        for (int k = 0; k < 32; k++) {
            const float4* arow = (const float4*)&As[k * PITCH];
            const float4* brow = (const float4*)&Bs[k * PITCH];
            float4 a0 = arow[ty * 2];
            float4 a1 = arow[ty * 2 + 1];
            float4 b0 = brow[tx];          // n = tx*4 .. +3
            float4 b1 = brow[tx + 16];     // n = 64 + tx*4 .. +3
            unsigned long long bp[4] = {pk2(b0.x, b0.y), pk2(b0.z, b0.w),
                                        pk2(b1.x, b1.y), pk2(b1.z, b1.w)};
            float aa[8] = {a0.x, a0.y, a0.z, a0.w, a1.x, a1.y, a1.z, a1.w};
            #pragma unroll
            for (int a = 0; a < 8; a++) {
                unsigned long long ad = pk2(aa[a], aa[a]);
                #pragma unroll
                for (int b2 = 0; b2 < 4; b2++) fma2(acc[a][b2], ad, bp[b2]);
            }
        }
        __syncthreads();
    }

    // Epilogue: write y only
    #pragma unroll
    for (int a = 0; a < 8; a++) {
        int gm = rowBase + ty * 8 + a;
        if (gm < M) {
            float2 r0 = up2(acc[a][0]), r1 = up2(acc[a][1]);
            float2 r2 = up2(acc[a][2]), r3 = up2(acc[a][3]);
            float* yrow = g_y + (size_t)gm * DIM;
            *(float4*)(yrow + tx * 4)      = make_float4(r0.x, r0.y, r1.x, r1.y);
            *(float4*)(yrow + 64 + tx * 4) = make_float4(r2.x, r2.y, r3.x, r3.y);
        }
    }
}

// ---------------- pull-aggregation: warp per node -------------------------
// out[t] = dinv[t]^2 * y[t] + bias + sum_{edges into t} wn * y[src]
__global__ void k_aggregate(const float* __restrict__ bias,
                            float* __restrict__ out, int n) {
    int warp = (blockIdx.x * blockDim.x + threadIdx.x) >> 5;
    int lane = threadIdx.x & 31;
    if (warp >= n) return;
    int t = warp;

    int beg = g_rowptr[t];
    int end = g_rowptr[t + 1];
    const float4* y4 = (const float4*)g_y;

    float di = g_dinv[t];
    float sc = di * di;
    float4 self = y4[(size_t)t * 32 + lane];
    float4 bi = ((const float4*)bias)[lane];
    float4 acc;
    acc.x = self.x * sc + bi.x;
    acc.y = self.y * sc + bi.y;
    acc.z = self.z * sc + bi.z;
    acc.w = self.w * sc + bi.w;

    // 1-deep software pipeline on the (src, wn) metadata
    int   s_nxt = 0;
    float w_nxt = 0.f;
    if (beg < end) { s_nxt = g_esrc[beg]; w_nxt = g_ewn[beg]; }
    for (int i = beg; i < end; i++) {
        int s = s_nxt;
        float wn = w_nxt;
        if (i + 1 < end) { s_nxt = g_esrc[i + 1]; w_nxt = g_ewn[i + 1]; }
        float4 v = y4[(size_t)s * 32 + lane];
        acc.x += v.x * wn;
        acc.y += v.y * wn;
        acc.z += v.z * wn;
        acc.w += v.w * wn;
    }
    ((float4*)out)[(size_t)t * 32 + lane] = acc;
    if (lane == 0) g_cnt[t] = 0;     // restore zero for next call
}

extern "C" void kernel_launch(void* const* d_in, const int* in_sizes, int n_in,
                              void* d_out, int out_size) {
    const float* x  = (const float*)d_in[0];
    const void*  ei = d_in[1];                 // [2, E] int32 OR int64
    const float* ew = (const float*)d_in[2];
    const float* W  = (const float*)d_in[3];
    const float* b  = (const float*)d_in[4];
    float* out = (float*)d_out;

    int N = in_sizes[0] / DIM;
    int E = in_sizes[1] / 2;
    int NB = (N + 255) / 256;
    int detect_cnt = (E < 1024) ? E : 1024;

    k_gemm<<<(N + 127) / 128, 256>>>(x, W, N);               // 0 (independent)
    k_detect<<<1, 256>>>(ei, N, detect_cnt);                 // 1
    k_edge_deg<<<(E + 255) / 256, 256>>>(ei, ew, E);         // 2
    k_scan1<<<NB, 256>>>(N);                                 // 3
    k_scan3<<<NB, 256>>>(N, NB, E);                          // 4
    k_fill<<<(E + 255) / 256, 256>>>(ei, ew, E);             // 5
    k_aggregate<<<(N * 32 + 255) / 256, 256>>>(b, out, N);   // 6
}

// round 6
// speedup vs baseline: 1.6275x; 1.1993x over previous
#include <cuda_runtime.h>
#include <cuda_bf16.h>
#include <cstdint>

#define N_NODES 50000
#define N_EDGES 600000
#define DIM 128
#define CAP 64
#define OVMAX 8192

// Device scratch (zero-init at load; invariants restored each call)
__device__ float g_deg[N_NODES];                    // reset in k_dinv
__device__ float g_dinv[N_NODES];
__device__ float g_y[(size_t)N_NODES * DIM];        // y = x @ W^T
__device__ int   g_cnt[N_NODES];                    // reset in k_aggregate
__device__ int2  g_ebuck[(size_t)N_NODES * CAP];    // (src, bits(w)) per target bucket
__device__ int   g_ovcnt;                           // overflow counter (reset in k_dinv)
__device__ int   g_ovuse;                           // latched count for aggregate
__device__ int   g_ovt[OVMAX];
__device__ int2  g_ovsw[OVMAX];

// ---------------- packed fp32x2 helpers ----------------
__device__ __forceinline__ unsigned long long pk2(float lo, float hi) {
    unsigned long long r;
    asm("mov.b64 %0, {%1, %2};" : "=l"(r) : "f"(lo), "f"(hi));
    return r;
}
__device__ __forceinline__ void fma2(unsigned long long& d,
                                     unsigned long long a, unsigned long long b) {
    asm("fma.rn.f32x2 %0, %1, %2, %0;" : "+l"(d) : "l"(a), "l"(b));
}
__device__ __forceinline__ float2 up2(unsigned long long v) {
    float2 f;
    asm("mov.b64 {%0, %1}, %2;" : "=f"(f.x), "=f"(f.y) : "l"(v));
    return f;
}

// =====================================================================
// Kernel A (fused): blocks [0,GB) = GEMM y = x@W^T
//                   blocks [GB,GB+EB) = edge pass (detect + deg + buckets)
// =====================================================================
#define PITCH 132
__global__ __launch_bounds__(256, 2) void k_fused(const float* __restrict__ x,
                                                  const float* __restrict__ W,
                                                  const void* __restrict__ ei,
                                                  const float* __restrict__ ew,
                                                  int M, int E, int GB, int EB) {
    if ((int)blockIdx.x < GB) {
        // ---------------- GEMM tile ----------------
        __shared__ float As[32 * PITCH];   // As[k][m]
        __shared__ float Bs[32 * PITCH];   // Bs[k][n] = W[n][k]

        int tid = threadIdx.x;
        int tx = tid & 15;
        int ty = tid >> 4;
        int rowBase = blockIdx.x * 128;
        int lm = tid >> 3;
        int kq = tid & 7;

        unsigned long long acc[8][4];
        #pragma unroll
        for (int a = 0; a < 8; a++)
            #pragma unroll
            for (int b2 = 0; b2 < 4; b2++) acc[a][b2] = 0ULL;

        float4 pA[4], pB[4];
        #pragma unroll
        for (int j = 0; j < 4; j++) {
            int m = lm + j * 32;
            int gm = rowBase + m;
            pA[j] = (gm < M) ? *(const float4*)(x + (size_t)gm * DIM + kq * 4)
                             : make_float4(0.f, 0.f, 0.f, 0.f);
            pB[j] = *(const float4*)(W + (size_t)m * DIM + kq * 4);
        }

        #pragma unroll
        for (int kt = 0; kt < DIM; kt += 32) {
            #pragma unroll
            for (int j = 0; j < 4; j++) {
                int m = lm + j * 32;
                As[(kq * 4 + 0) * PITCH + m] = pA[j].x;
                As[(kq * 4 + 1) * PITCH + m] = pA[j].y;
                As[(kq * 4 + 2) * PITCH + m] = pA[j].z;
                As[(kq * 4 + 3) * PITCH + m] = pA[j].w;
                Bs[(kq * 4 + 0) * PITCH + m] = pB[j].x;
                Bs[(kq * 4 + 1) * PITCH + m] = pB[j].y;
                Bs[(kq * 4 + 2) * PITCH + m] = pB[j].z;
                Bs[(kq * 4 + 3) * PITCH + m] = pB[j].w;
            }
            __syncthreads();

            if (kt + 32 < DIM) {
                #pragma unroll
                for (int j = 0; j < 4; j++) {
                    int m = lm + j * 32;
                    int gm = rowBase + m;
                    pA[j] = (gm < M) ? *(const float4*)(x + (size_t)gm * DIM + kt + 32 + kq * 4)
                                     : make_float4(0.f, 0.f, 0.f, 0.f);
                    pB[j] = *(const float4*)(W + (size_t)m * DIM + kt + 32 + kq * 4);
                }
            }

            #pragma unroll
            for (int k = 0; k < 32; k++) {
                const float4* arow = (const float4*)&As[k * PITCH];
                const float4* brow = (const float4*)&Bs[k * PITCH];
                float4 a0 = arow[ty * 2];
                float4 a1 = arow[ty * 2 + 1];
                float4 b0 = brow[tx];          // n = tx*4
                float4 b1 = brow[tx + 16];     // n = 64 + tx*4
                unsigned long long bp[4] = {pk2(b0.x, b0.y), pk2(b0.z, b0.w),
                                            pk2(b1.x, b1.y), pk2(b1.z, b1.w)};
                float aa[8] = {a0.x, a0.y, a0.z, a0.w, a1.x, a1.y, a1.z, a1.w};
                #pragma unroll
                for (int a = 0; a < 8; a++) {
                    unsigned long long ad = pk2(aa[a], aa[a]);
                    #pragma unroll
                    for (int b2 = 0; b2 < 4; b2++) fma2(acc[a][b2], ad, bp[b2]);
                }
            }
            __syncthreads();
        }

        #pragma unroll
        for (int a = 0; a < 8; a++) {
            int gm = rowBase + ty * 8 + a;
            if (gm < M) {
                float2 r0 = up2(acc[a][0]), r1 = up2(acc[a][1]);
                float2 r2 = up2(acc[a][2]), r3 = up2(acc[a][3]);
                float* yrow = g_y + (size_t)gm * DIM;
                *(float4*)(yrow + tx * 4)      = make_float4(r0.x, r0.y, r1.x, r1.y);
                *(float4*)(yrow + 64 + tx * 4) = make_float4(r2.x, r2.y, r3.x, r3.y);
            }
        }
    } else {
        // ---------------- edge pass ----------------
        int b = blockIdx.x - GB;
        if (b >= EB) return;
        int chunk = (E + EB - 1) / EB;
        int beg = b * chunk;
        int end = beg + chunk; if (end > E) end = E;
        if (beg >= end) return;

        // per-block dtype detect on own chunk (int32 read as int64 has a
        // nonzero high word w.p. ~1 among 256 samples)
        __shared__ int s_is64;
        if (threadIdx.x == 0) s_is64 = 1;
        __syncthreads();
        const long long* p64 = (const long long*)ei;
        const int*       p32 = (const int*)ei;
        int samp = end - beg; if (samp > 256) samp = 256;
        if ((int)threadIdx.x < samp) {
            long long v = p64[beg + threadIdx.x];
            if (v < 0 || v >= (long long)N_NODES) s_is64 = 0;
        }
        __syncthreads();
        int is64 = s_is64;

        for (int i = beg + threadIdx.x; i < end; i += 256) {
            int s, t;
            float w = ew[i];
            if (is64) { s = (int)p64[i]; t = (int)p64[(size_t)E + i]; }
            else      { s = p32[i];      t = p32[(size_t)E + i]; }
            atomicAdd(&g_deg[s], w);
            int pos = atomicAdd(&g_cnt[t], 1);
            if (pos < CAP) {
                g_ebuck[(size_t)t * CAP + pos] = make_int2(s, __float_as_int(w));
            } else {
                int o = atomicAdd(&g_ovcnt, 1);
                if (o < OVMAX) { g_ovt[o] = t; g_ovsw[o] = make_int2(s, __float_as_int(w)); }
            }
        }
    }
}

// ---------------- dinv = rsqrt(deg + 1); reset deg; latch overflow --------
__global__ void k_dinv(int n) {
    int i = blockIdx.x * blockDim.x + threadIdx.x;
    if (i < n) {
        g_dinv[i] = rsqrtf(g_deg[i] + 1.0f);   // +1 = self-loop
        g_deg[i] = 0.0f;
    }
    if (i == 0) {
        int c = g_ovcnt;
        g_ovuse = (c < OVMAX) ? c : OVMAX;
        g_ovcnt = 0;
    }
}

// ---------------- pull-aggregation: warp per node -------------------------
__global__ void k_aggregate(const float* __restrict__ bias,
                            float* __restrict__ out, int n) {
    int warp = (blockIdx.x * blockDim.x + threadIdx.x) >> 5;
    int lane = threadIdx.x & 31;
    if (warp >= n) return;
    int t = warp;

    int cnt = g_cnt[t];
    if (cnt > CAP) cnt = CAP;
    const float4* y4 = (const float4*)g_y;
    const int2* buck = g_ebuck + (size_t)t * CAP;

    float di = g_dinv[t];
    float sc = di * di;
    float4 self = y4[(size_t)t * 32 + lane];
    float4 bi = ((const float4*)bias)[lane];
    float4 acc;
    acc.x = self.x * sc + bi.x;
    acc.y = self.y * sc + bi.y;
    acc.z = self.z * sc + bi.z;
    acc.w = self.w * sc + bi.w;

    // 1-deep prefetch on bucket metadata
    int2 e_nxt = make_int2(0, 0);
    if (cnt > 0) e_nxt = buck[0];
    for (int j = 0; j < cnt; j++) {
        int2 e = e_nxt;
        if (j + 1 < cnt) e_nxt = buck[j + 1];
        float wn = __int_as_float(e.y) * g_dinv[e.x] * di;
        float4 v = y4[(size_t)e.x * 32 + lane];
        acc.x += v.x * wn;
        acc.y += v.y * wn;
        acc.z += v.z * wn;
        acc.w += v.w * wn;
    }

    // overflow tail (normally empty)
    int ov = g_ovuse;
    for (int i = 0; i < ov; i++) {
        if (g_ovt[i] == t) {
            int2 e = g_ovsw[i];
            float wn = __int_as_float(e.y) * g_dinv[e.x] * di;
            float4 v = y4[(size_t)e.x * 32 + lane];
            acc.x += v.x * wn;
            acc.y += v.y * wn;
            acc.z += v.z * wn;
            acc.w += v.w * wn;
        }
    }

    ((float4*)out)[(size_t)t * 32 + lane] = acc;
    if (lane == 0) g_cnt[t] = 0;     // restore zero for next call
}

extern "C" void kernel_launch(void* const* d_in, const int* in_sizes, int n_in,
                              void* d_out, int out_size) {
    const float* x  = (const float*)d_in[0];
    const void*  ei = d_in[1];                 // [2, E] int32 OR int64
    const float* ew = (const float*)d_in[2];
    const float* W  = (const float*)d_in[3];
    const float* b  = (const float*)d_in[4];
    float* out = (float*)d_out;

    int N = in_sizes[0] / DIM;
    int E = in_sizes[1] / 2;

    int GB = (N + 127) / 128;       // GEMM tiles
    int EB = 296;                   // edge blocks (one extra wave's worth)

    k_fused<<<GB + EB, 256>>>(x, W, ei, ew, N, E, GB, EB);     // 0
    k_dinv<<<(N + 255) / 256, 256>>>(N);                       // 1
    k_aggregate<<<(N * 32 + 255) / 256, 256>>>(b, out, N);     // 2
}